// round 16
// baseline (speedup 1.0000x reference)
#include <cuda_runtime.h>
#include <cuda_fp16.h>
#include <cstdint>

// Problem constants
#define BATCH 32
#define NNODE 4096
#define INDIM 64
#define HDIM  128
#define BNHs ((size_t)BATCH * NNODE * HDIM)

// fp16 GEMM tile config
#define BM 128
#define BN 128
#define BK 32
#define NSTAGE 4
#define SA_H 40          // A row stride (halves) in pipeline stages
#define SB_H 136         // B/W/aggS row stride (halves)
#define STAGE_BYTES 18944
#define PIPE_BYTES (NSTAGE * STAGE_BYTES)       // 75776
#define WS_OFF PIPE_BYTES                        // W tile: 128 x 136 halves
#define FUSED_SMEM_BYTES (PIPE_BYTES + 128 * SB_H * 2)   // 110592 -> 2 CTAs/SM

#define ADJ_SCALE 4096.0f
#define INV_ADJ_SCALE 0.000244140625f            // 2^-12, exact

// ---------------------------------------------------------------------------
// fp16 global pool (~117.5 MB):
//   [0,        BNHs)   : tsh    (fp16 t — gcn1 output)
//   [BNHs,   2*BNHs)   : hsh    (fp16 shadow of h)
//   [2*BNHs, 3*BNHs)   : adj_h  (fp16 adj * 4096)
//   [3*BNHs, 3.5*BNHs) : x_h
//   [3.5*BNHs, +40960) : W_fc | W1 | W2 (fp16)
// RACE-FREE: every launch's fp16 input buffer != its fp16 output buffer.
// fp32 Euler state h lives in d_out.
// ---------------------------------------------------------------------------
__device__ __align__(256) __half g_h16[(BNHs * 7) / 2 + 40960];

__global__ void convert_half_kernel(const float* __restrict__ in, __half* __restrict__ out,
                                    int n4, float scale) {
    int i = blockIdx.x * blockDim.x + threadIdx.x;
    if (i < n4) {
        float4 v = reinterpret_cast<const float4*>(in)[i];
        __half2 p0 = __floats2half2_rn(v.x * scale, v.y * scale);
        __half2 p1 = __floats2half2_rn(v.z * scale, v.w * scale);
        uint2 u;
        u.x = *reinterpret_cast<uint32_t*>(&p0);
        u.y = *reinterpret_cast<uint32_t*>(&p1);
        reinterpret_cast<uint2*>(out)[i] = u;
    }
}

__device__ __forceinline__ void cp_async16(uint32_t smem, const void* gmem) {
    asm volatile("cp.async.cg.shared.global [%0], [%1], 16;\n" :: "r"(smem), "l"(gmem));
}
#define CP_COMMIT() asm volatile("cp.async.commit_group;\n" ::: "memory")
#define CP_WAIT0()  asm volatile("cp.async.wait_group 0;\n" ::: "memory")
#define CP_WAIT2()  asm volatile("cp.async.wait_group 2;\n" ::: "memory")

__device__ __forceinline__ void ldsm_x4(uint32_t* r, uint32_t addr) {
    asm volatile("ldmatrix.sync.aligned.m8n8.x4.shared.b16 {%0,%1,%2,%3}, [%4];"
                 : "=r"(r[0]), "=r"(r[1]), "=r"(r[2]), "=r"(r[3]) : "r"(addr));
}
__device__ __forceinline__ void ldsm_x4_t(uint32_t* r, uint32_t addr) {
    asm volatile("ldmatrix.sync.aligned.m8n8.x4.trans.shared.b16 {%0,%1,%2,%3}, [%4];"
                 : "=r"(r[0]), "=r"(r[1]), "=r"(r[2]), "=r"(r[3]) : "r"(addr));
}
__device__ __forceinline__ void mma_fp16(float c[4], const uint32_t a[4],
                                         uint32_t b0, uint32_t b1) {
    asm volatile(
        "mma.sync.aligned.m16n8k16.row.col.f32.f16.f16.f32 "
        "{%0,%1,%2,%3}, {%4,%5,%6,%7}, {%8,%9}, {%0,%1,%2,%3};\n"
        : "+f"(c[0]), "+f"(c[1]), "+f"(c[2]), "+f"(c[3])
        : "r"(a[0]), "r"(a[1]), "r"(a[2]), "r"(a[3]), "r"(b0), "r"(b1));
}

// ===========================================================================
// Fused GCN layer: per CTA (128 nodes x 128 hidden, batch z):
//   agg  = (adj_h[rows,:] @ Hin16[z]) * 2^-12        (K=4096 fp16 mainloop)
//   proj = agg16 @ W                                 (K=128, on-chip)
//   EULER==0: Hout16 = fp16(relu(proj + bias))
//   EULER==1: hn = h + 0.25*relu(proj + bias); h = hn; Hout16 = fp16(hn)
// Hin16 and Hout16 are DISTINCT buffers (race-free).
// ===========================================================================
template <int EULER>
__global__ __launch_bounds__(256, 2)
void gcn_fused_kernel(const __half* __restrict__ A, const __half* __restrict__ Hin,
                      const __half* __restrict__ Wr, const float* __restrict__ bias,
                      __half* __restrict__ Hout, float* __restrict__ hGlob)
{
    extern __shared__ __align__(16) char dsm[];
    const uint32_t sb = (uint32_t)__cvta_generic_to_shared(dsm);

    const int tid  = threadIdx.x;
    const int lane = tid & 31;
    const int warp = tid >> 5;
    const int wm = (warp & 3) * 32;   // 4 warps along M
    const int wn = (warp >> 2) * 64;  // 2 warps along N
    const int g = lane >> 2;
    const int t = lane & 3;
    const int lrow = lane & 15;
    const int lhi  = lane >> 4;

    const int bm = blockIdx.y * BM;
    const int bz = blockIdx.z;
    const long long sNH = (long long)NNODE * HDIM;
    const __half* Ab = A + (long long)bm * NNODE;
    const __half* Bb = Hin + (long long)bz * sNH;
    __half* Chb = Hout + (long long)bz * sNH + (long long)bm * HDIM;
    float* hb = EULER ? (hGlob + (long long)bz * sNH + (long long)bm * HDIM) : nullptr;

    float acc[2][8][4];
    #pragma unroll
    for (int mt = 0; mt < 2; mt++)
        #pragma unroll
        for (int nt = 0; nt < 8; nt++)
            #pragma unroll
            for (int i = 0; i < 4; i++)
                acc[mt][nt][i] = 0.0f;

    auto load_stage = [&](int s, int kt) {
        const uint32_t abase = sb + s * STAGE_BYTES;
        #pragma unroll
        for (int i = 0; i < 2; i++) {
            int idx = tid + i * 256;
            int r = idx >> 2;
            int j = idx & 3;
            cp_async16(abase + r * 80 + j * 16,
                       Ab + (long long)r * NNODE + kt * 32 + j * 8);
        }
        const uint32_t bbase = abase + 10240;
        #pragma unroll
        for (int i = 0; i < 2; i++) {
            int idx = tid + i * 256;
            int r = idx >> 4;
            int j = idx & 15;
            cp_async16(bbase + r * 272 + j * 16,
                       Bb + (long long)(kt * 32 + r) * 128 + j * 8);
        }
        CP_COMMIT();
    };

    auto compute_stage = [&](int s) {
        const uint32_t abase = sb + s * STAGE_BYTES;
        const uint32_t bbase = abase + 10240;
        #pragma unroll
        for (int ks = 0; ks < 32; ks += 16) {
            uint32_t af[2][4];
            #pragma unroll
            for (int mt = 0; mt < 2; mt++) {
                uint32_t addr = abase +
                    2u * ((wm + mt * 16 + lrow) * SA_H + ks + 8 * lhi);
                ldsm_x4(af[mt], addr);
            }
            #pragma unroll
            for (int np = 0; np < 4; np++) {
                uint32_t bf[4];
                uint32_t addr = bbase +
                    2u * ((ks + lrow) * SB_H + wn + np * 16 + 8 * lhi);
                ldsm_x4_t(bf, addr);
                #pragma unroll
                for (int mt = 0; mt < 2; mt++) {
                    mma_fp16(acc[mt][2 * np + 0], af[mt], bf[0], bf[1]);
                    mma_fp16(acc[mt][2 * np + 1], af[mt], bf[2], bf[3]);
                }
            }
        }
    };

    // Prologue: W tile joins stage 0's commit group.
    {
        const uint32_t wbase = sb + WS_OFF;
        #pragma unroll
        for (int i = 0; i < 8; i++) {
            int idx = tid + i * 256;
            int r = idx >> 4;
            int j = idx & 15;
            cp_async16(wbase + r * 272 + j * 16, Wr + r * 128 + j * 8);
        }
    }
    load_stage(0, 0);      // commits W + stage0 together
    load_stage(1, 1);
    load_stage(2, 2);
    CP_WAIT2();
    __syncthreads();

    const int nk = NNODE / BK;   // 128
    for (int kt = 0; kt < nk; kt++) {
        compute_stage(kt & 3);
        if (kt + 1 < nk) {
            if (kt + 3 < nk) {
                load_stage((kt + 3) & 3, kt + 3);
                CP_WAIT2();
            } else {
                CP_WAIT0();
            }
            __syncthreads();
        }
    }

    // ---- stage fp16(agg * 2^-12) into smem (dead pipeline region) ----
    __syncthreads();
    #pragma unroll
    for (int mt = 0; mt < 2; mt++) {
        #pragma unroll
        for (int nt = 0; nt < 8; nt++) {
            #pragma unroll
            for (int h2 = 0; h2 < 2; h2++) {
                const int row = wm + mt * 16 + g + h2 * 8;
                const int col = wn + nt * 8 + t * 2;
                __half2 v = __floats2half2_rn(acc[mt][nt][h2 * 2 + 0] * INV_ADJ_SCALE,
                                              acc[mt][nt][h2 * 2 + 1] * INV_ADJ_SCALE);
                *reinterpret_cast<__half2*>(dsm + row * (SB_H * 2) + col * 2) = v;
            }
        }
    }
    __syncthreads();

    // ---- on-chip projection: acc = aggS @ W  (K = 128) ----
    #pragma unroll
    for (int mt = 0; mt < 2; mt++)
        #pragma unroll
        for (int nt = 0; nt < 8; nt++)
            #pragma unroll
            for (int i = 0; i < 4; i++)
                acc[mt][nt][i] = 0.0f;

    #pragma unroll
    for (int ks = 0; ks < HDIM; ks += 16) {
        uint32_t af[2][4];
        #pragma unroll
        for (int mt = 0; mt < 2; mt++) {
            uint32_t addr = sb + 2u * ((wm + mt * 16 + lrow) * SB_H + ks + 8 * lhi);
            ldsm_x4(af[mt], addr);
        }
        #pragma unroll
        for (int np = 0; np < 4; np++) {
            uint32_t bf[4];
            uint32_t addr = sb + WS_OFF +
                2u * ((ks + lrow) * SB_H + wn + np * 16 + 8 * lhi);
            ldsm_x4_t(bf, addr);
            #pragma unroll
            for (int mt = 0; mt < 2; mt++) {
                mma_fp16(acc[mt][2 * np + 0], af[mt], bf[0], bf[1]);
                mma_fp16(acc[mt][2 * np + 1], af[mt], bf[2], bf[3]);
            }
        }
    }

    // ---- final epilogue ----
    #pragma unroll
    for (int mt = 0; mt < 2; mt++) {
        #pragma unroll
        for (int nt = 0; nt < 8; nt++) {
            #pragma unroll
            for (int h2 = 0; h2 < 2; h2++) {
                const int row = wm + mt * 16 + g + h2 * 8;
                const int col = wn + nt * 8 + t * 2;
                float v0 = acc[mt][nt][h2 * 2 + 0] + bias[col];
                float v1 = acc[mt][nt][h2 * 2 + 1] + bias[col + 1];
                const long long off = (long long)row * HDIM + col;
                if (EULER == 0) {
                    v0 = fmaxf(v0, 0.0f);
                    v1 = fmaxf(v1, 0.0f);
                    *reinterpret_cast<__half2*>(&Chb[off]) = __floats2half2_rn(v0, v1);
                } else {
                    float2 hin = *reinterpret_cast<const float2*>(&hb[off]);
                    float2 o = { hin.x + 0.25f * fmaxf(v0, 0.0f),
                                 hin.y + 0.25f * fmaxf(v1, 0.0f) };
                    *reinterpret_cast<float2*>(&hb[off]) = o;
                    *reinterpret_cast<__half2*>(&Chb[off]) = __floats2half2_rn(o.x, o.y);
                }
            }
        }
    }
}

// ===========================================================================
// fc kernel: h = x @ W_fc + b_fc (fp32 out + fp16 shadow). K = 64, 2 stages.
// ===========================================================================
__global__ __launch_bounds__(256, 2)
void fc_kernel(const __half* __restrict__ A, const __half* __restrict__ Bg,
               float* __restrict__ Cf, __half* __restrict__ Ch,
               const float* __restrict__ bias)
{
    extern __shared__ __align__(16) char dsm[];
    const uint32_t sb = (uint32_t)__cvta_generic_to_shared(dsm);
    const int K = INDIM;

    const int tid  = threadIdx.x;
    const int lane = tid & 31;
    const int warp = tid >> 5;
    const int wm = (warp & 3) * 32;
    const int wn = (warp >> 2) * 64;
    const int g = lane >> 2;
    const int t = lane & 3;
    const int lrow = lane & 15;
    const int lhi  = lane >> 4;

    const int bm = blockIdx.y * BM;
    const __half* Ab = A + (long long)bm * K;

    float acc[2][8][4];
    #pragma unroll
    for (int mt = 0; mt < 2; mt++)
        #pragma unroll
        for (int nt = 0; nt < 8; nt++)
            #pragma unroll
            for (int i = 0; i < 4; i++)
                acc[mt][nt][i] = 0.0f;

    auto load_stage = [&](int s, int kt) {
        const uint32_t abase = sb + s * STAGE_BYTES;
        #pragma unroll
        for (int i = 0; i < 2; i++) {
            int idx = tid + i * 256;
            int r = idx >> 2;
            int j = idx & 3;
            cp_async16(abase + r * 80 + j * 16,
                       Ab + (long long)r * K + kt * 32 + j * 8);
        }
        const uint32_t bbase = abase + 10240;
        #pragma unroll
        for (int i = 0; i < 2; i++) {
            int idx = tid + i * 256;
            int r = idx >> 4;
            int j = idx & 15;
            cp_async16(bbase + r * 272 + j * 16,
                       Bg + (long long)(kt * 32 + r) * 128 + j * 8);
        }
        CP_COMMIT();
    };

    auto compute_stage = [&](int s) {
        const uint32_t abase = sb + s * STAGE_BYTES;
        const uint32_t bbase = abase + 10240;
        #pragma unroll
        for (int ks = 0; ks < 32; ks += 16) {
            uint32_t af[2][4];
            #pragma unroll
            for (int mt = 0; mt < 2; mt++) {
                uint32_t addr = abase +
                    2u * ((wm + mt * 16 + lrow) * SA_H + ks + 8 * lhi);
                ldsm_x4(af[mt], addr);
            }
            #pragma unroll
            for (int np = 0; np < 4; np++) {
                uint32_t bf[4];
                uint32_t addr = bbase +
                    2u * ((ks + lrow) * SB_H + wn + np * 16 + 8 * lhi);
                ldsm_x4_t(bf, addr);
                #pragma unroll
                for (int mt = 0; mt < 2; mt++) {
                    mma_fp16(acc[mt][2 * np + 0], af[mt], bf[0], bf[1]);
                    mma_fp16(acc[mt][2 * np + 1], af[mt], bf[2], bf[3]);
                }
            }
        }
    };

    load_stage(0, 0);
    load_stage(1, 1);
    CP_WAIT0();
    __syncthreads();
    compute_stage(0);
    compute_stage(1);

    #pragma unroll
    for (int mt = 0; mt < 2; mt++) {
        #pragma unroll
        for (int nt = 0; nt < 8; nt++) {
            #pragma unroll
            for (int h2 = 0; h2 < 2; h2++) {
                const int row = bm + wm + mt * 16 + g + h2 * 8;
                const int col = wn + nt * 8 + t * 2;
                float2 o = { acc[mt][nt][h2 * 2 + 0] + bias[col],
                             acc[mt][nt][h2 * 2 + 1] + bias[col + 1] };
                const long long off = (long long)row * HDIM + col;
                *reinterpret_cast<float2*>(&Cf[off]) = o;
                *reinterpret_cast<__half2*>(&Ch[off]) = __floats2half2_rn(o.x, o.y);
            }
        }
    }
}

extern "C" void kernel_launch(void* const* d_in, const int* in_sizes, int n_in,
                              void* d_out, int out_size)
{
    const float* x    = (const float*)d_in[0];
    const float* adj  = (const float*)d_in[1];
    const float* W_fc = (const float*)d_in[2];
    const float* b_fc = (const float*)d_in[3];
    const float* W1   = (const float*)d_in[4];
    const float* b1   = (const float*)d_in[5];
    const float* W2   = (const float*)d_in[6];
    const float* b2   = (const float*)d_in[7];
    float* out = (float*)d_out;

    __half* base;
    cudaGetSymbolAddress((void**)&base, g_h16);
    __half* tsh   = base;                      // fp16 t (gcn1 output)
    __half* hsh   = base + BNHs;               // fp16 shadow of h
    __half* adj_h = base + 2 * BNHs;
    __half* x_h   = base + 3 * BNHs;
    __half* wfc_h = base + 3 * BNHs + BNHs / 2;
    __half* w1_h  = wfc_h + INDIM * HDIM;
    __half* w2_h  = w1_h + HDIM * HDIM;
    float* h = out;    // fp32 Euler state

    cudaFuncSetAttribute(gcn_fused_kernel<0>, cudaFuncAttributeMaxDynamicSharedMemorySize, FUSED_SMEM_BYTES);
    cudaFuncSetAttribute(gcn_fused_kernel<1>, cudaFuncAttributeMaxDynamicSharedMemorySize, FUSED_SMEM_BYTES);
    cudaFuncSetAttribute(fc_kernel, cudaFuncAttributeMaxDynamicSharedMemorySize, 2 * STAGE_BYTES);

    // fp32 -> fp16 conversions (adj pre-scaled by 4096).
    {
        const int thr = 256;
        int n4 = (NNODE * NNODE) / 4;
        convert_half_kernel<<<(n4 + thr - 1) / thr, thr>>>(adj, adj_h, n4, ADJ_SCALE);
        n4 = (BATCH * NNODE * INDIM) / 4;
        convert_half_kernel<<<(n4 + thr - 1) / thr, thr>>>(x, x_h, n4, 1.0f);
        n4 = (INDIM * HDIM) / 4;
        convert_half_kernel<<<(n4 + thr - 1) / thr, thr>>>(W_fc, wfc_h, n4, 1.0f);
        n4 = (HDIM * HDIM) / 4;
        convert_half_kernel<<<(n4 + thr - 1) / thr, thr>>>(W1, w1_h, n4, 1.0f);
        convert_half_kernel<<<(n4 + thr - 1) / thr, thr>>>(W2, w2_h, n4, 1.0f);
    }

    dim3 blk(256);
    const dim3 fgrid(1, NNODE / BM, BATCH);

    // h = x @ W_fc + b_fc  (fp32 h + fp16 shadow hsh)
    fc_kernel<<<dim3(1, (BATCH * NNODE) / BM, 1), blk, 2 * STAGE_BYTES>>>(
        x_h, wfc_h, h, hsh, b_fc);

    for (int step = 0; step < 4; step++) {
        // tsh = fp16(relu((adj @ hsh) @ W1 + b1))      [reads hsh, writes tsh]
        gcn_fused_kernel<0><<<fgrid, blk, FUSED_SMEM_BYTES>>>(
            adj_h, hsh, w1_h, b1, tsh, nullptr);
        // h += 0.25*relu((adj @ tsh) @ W2 + b2); hsh = fp16(h)   [reads tsh, writes hsh]
        gcn_fused_kernel<1><<<fgrid, blk, FUSED_SMEM_BYTES>>>(
            adj_h, tsh, w2_h, b2, hsh, h);
    }
}

// round 17
// speedup vs baseline: 1.0005x; 1.0005x over previous
#include <cuda_runtime.h>
#include <cuda_fp16.h>
#include <cstdint>

// Problem constants
#define BATCH 32
#define NNODE 4096
#define INDIM 64
#define HDIM  128
#define BNHs ((size_t)BATCH * NNODE * HDIM)

// fp16 GEMM tile config
#define BM 128
#define BN 128
#define BK 32
#define NSTAGE 5
#define SA_H 40          // A row stride (halves) in pipeline stages
#define SB_H 136         // B/W/aggS row stride (halves)
#define STAGE_BYTES 18944
#define PIPE_BYTES (NSTAGE * STAGE_BYTES)        // 94720 -> 2 CTAs/SM
#define WPROJ_OFF (2 * STAGE_BYTES)              // W tile loaded POST-mainloop
#define FUSED_SMEM_BYTES PIPE_BYTES

#define ADJ_SCALE 4096.0f
#define INV_ADJ_SCALE 0.000244140625f            // 2^-12, exact

// ---------------------------------------------------------------------------
// fp16 global pool (~117.5 MB):
//   [0,        BNHs)   : tsh    (fp16 t — gcn1 output)
//   [BNHs,   2*BNHs)   : hsh    (fp16 shadow of h)
//   [2*BNHs, 3*BNHs)   : adj_h  (fp16 adj * 4096)
//   [3*BNHs, 3.5*BNHs) : x_h
//   [3.5*BNHs, +40960) : W_fc | W1 | W2 (fp16)
// RACE-FREE: every launch's fp16 input buffer != its fp16 output buffer.
// fp32 Euler state h lives in d_out.
// ---------------------------------------------------------------------------
__device__ __align__(256) __half g_h16[(BNHs * 7) / 2 + 40960];

__global__ void convert_half_kernel(const float* __restrict__ in, __half* __restrict__ out,
                                    int n4, float scale) {
    int i = blockIdx.x * blockDim.x + threadIdx.x;
    if (i < n4) {
        float4 v = reinterpret_cast<const float4*>(in)[i];
        __half2 p0 = __floats2half2_rn(v.x * scale, v.y * scale);
        __half2 p1 = __floats2half2_rn(v.z * scale, v.w * scale);
        uint2 u;
        u.x = *reinterpret_cast<uint32_t*>(&p0);
        u.y = *reinterpret_cast<uint32_t*>(&p1);
        reinterpret_cast<uint2*>(out)[i] = u;
    }
}

__device__ __forceinline__ void cp_async16(uint32_t smem, const void* gmem) {
    asm volatile("cp.async.cg.shared.global [%0], [%1], 16;\n" :: "r"(smem), "l"(gmem));
}
#define CP_COMMIT() asm volatile("cp.async.commit_group;\n" ::: "memory")
#define CP_WAIT0()  asm volatile("cp.async.wait_group 0;\n" ::: "memory")
#define CP_WAIT1()  asm volatile("cp.async.wait_group 1;\n" ::: "memory")
#define CP_WAIT2()  asm volatile("cp.async.wait_group 2;\n" ::: "memory")
#define CP_WAIT3()  asm volatile("cp.async.wait_group 3;\n" ::: "memory")

__device__ __forceinline__ void ldsm_x4(uint32_t* r, uint32_t addr) {
    asm volatile("ldmatrix.sync.aligned.m8n8.x4.shared.b16 {%0,%1,%2,%3}, [%4];"
                 : "=r"(r[0]), "=r"(r[1]), "=r"(r[2]), "=r"(r[3]) : "r"(addr));
}
__device__ __forceinline__ void ldsm_x4_t(uint32_t* r, uint32_t addr) {
    asm volatile("ldmatrix.sync.aligned.m8n8.x4.trans.shared.b16 {%0,%1,%2,%3}, [%4];"
                 : "=r"(r[0]), "=r"(r[1]), "=r"(r[2]), "=r"(r[3]) : "r"(addr));
}
__device__ __forceinline__ void mma_fp16(float c[4], const uint32_t a[4],
                                         uint32_t b0, uint32_t b1) {
    asm volatile(
        "mma.sync.aligned.m16n8k16.row.col.f32.f16.f16.f32 "
        "{%0,%1,%2,%3}, {%4,%5,%6,%7}, {%8,%9}, {%0,%1,%2,%3};\n"
        : "+f"(c[0]), "+f"(c[1]), "+f"(c[2]), "+f"(c[3])
        : "r"(a[0]), "r"(a[1]), "r"(a[2]), "r"(a[3]), "r"(b0), "r"(b1));
}

// ===========================================================================
// Fused GCN layer: per CTA (128 nodes x 128 hidden, batch z):
//   agg  = (adj_h[rows,:] @ Hin16[z]) * 2^-12        (K=4096, 5-stage pipeline)
//   proj = agg16 @ W                                 (K=128, on-chip; W loaded
//                                                     post-mainloop from L2)
//   EULER==0: Hout16 = fp16(relu(proj + bias))
//   EULER==1: hn = h + 0.25*relu(proj + bias); h = hn; Hout16 = fp16(hn)
// Hin16 and Hout16 are DISTINCT buffers (race-free).
// ===========================================================================
template <int EULER>
__global__ __launch_bounds__(256, 2)
void gcn_fused_kernel(const __half* __restrict__ A, const __half* __restrict__ Hin,
                      const __half* __restrict__ Wr, const float* __restrict__ bias,
                      __half* __restrict__ Hout, float* __restrict__ hGlob)
{
    extern __shared__ __align__(16) char dsm[];
    const uint32_t sb = (uint32_t)__cvta_generic_to_shared(dsm);

    const int tid  = threadIdx.x;
    const int lane = tid & 31;
    const int warp = tid >> 5;
    const int wm = (warp & 3) * 32;   // 4 warps along M
    const int wn = (warp >> 2) * 64;  // 2 warps along N
    const int g = lane >> 2;
    const int t = lane & 3;
    const int lrow = lane & 15;
    const int lhi  = lane >> 4;

    const int bm = blockIdx.y * BM;
    const int bz = blockIdx.z;
    const long long sNH = (long long)NNODE * HDIM;
    const __half* Ab = A + (long long)bm * NNODE;
    const __half* Bb = Hin + (long long)bz * sNH;
    __half* Chb = Hout + (long long)bz * sNH + (long long)bm * HDIM;
    float* hb = EULER ? (hGlob + (long long)bz * sNH + (long long)bm * HDIM) : nullptr;

    float acc[2][8][4];
    #pragma unroll
    for (int mt = 0; mt < 2; mt++)
        #pragma unroll
        for (int nt = 0; nt < 8; nt++)
            #pragma unroll
            for (int i = 0; i < 4; i++)
                acc[mt][nt][i] = 0.0f;

    auto load_stage = [&](int s, int kt) {
        const uint32_t abase = sb + s * STAGE_BYTES;
        #pragma unroll
        for (int i = 0; i < 2; i++) {
            int idx = tid + i * 256;
            int r = idx >> 2;
            int j = idx & 3;
            cp_async16(abase + r * 80 + j * 16,
                       Ab + (long long)r * NNODE + kt * 32 + j * 8);
        }
        const uint32_t bbase = abase + 10240;
        #pragma unroll
        for (int i = 0; i < 2; i++) {
            int idx = tid + i * 256;
            int r = idx >> 4;
            int j = idx & 15;
            cp_async16(bbase + r * 272 + j * 16,
                       Bb + (long long)(kt * 32 + r) * 128 + j * 8);
        }
        CP_COMMIT();
    };

    auto compute_stage = [&](int s) {
        const uint32_t abase = sb + s * STAGE_BYTES;
        const uint32_t bbase = abase + 10240;
        #pragma unroll
        for (int ks = 0; ks < 32; ks += 16) {
            uint32_t af[2][4];
            #pragma unroll
            for (int mt = 0; mt < 2; mt++) {
                uint32_t addr = abase +
                    2u * ((wm + mt * 16 + lrow) * SA_H + ks + 8 * lhi);
                ldsm_x4(af[mt], addr);
            }
            #pragma unroll
            for (int np = 0; np < 4; np++) {
                uint32_t bf[4];
                uint32_t addr = bbase +
                    2u * ((ks + lrow) * SB_H + wn + np * 16 + 8 * lhi);
                ldsm_x4_t(bf, addr);
                #pragma unroll
                for (int mt = 0; mt < 2; mt++) {
                    mma_fp16(acc[mt][2 * np + 0], af[mt], bf[0], bf[1]);
                    mma_fp16(acc[mt][2 * np + 1], af[mt], bf[2], bf[3]);
                }
            }
        }
    };

    // Prologue: 4 stages in flight; wait until stage 0 complete (3 outstanding).
    load_stage(0, 0);
    load_stage(1, 1);
    load_stage(2, 2);
    load_stage(3, 3);
    CP_WAIT3();
    __syncthreads();

    const int nk = NNODE / BK;   // 128
    int cs = 0;                  // compute stage index (kt % 5)
    int ls = 4;                  // next load stage index ((kt+4) % 5)
    for (int kt = 0; kt < nk; kt++) {
        compute_stage(cs);
        if (++cs == NSTAGE) cs = 0;
        if (kt + 1 < nk) {
            if (kt + 4 < nk) {
                load_stage(ls, kt + 4);
                if (++ls == NSTAGE) ls = 0;
                CP_WAIT3();          // stage kt+1 complete (depth-3 lookahead)
            } else if (kt + 4 == nk) {
                CP_WAIT2();
            } else if (kt + 3 == nk) {
                CP_WAIT1();
            } else {
                CP_WAIT0();
            }
            __syncthreads();
        }
    }

    // ---- post-mainloop: kick W load (L2-hot) into stages 2-3 region, then
    //      stage fp16(agg * 2^-12) into stages 0-1 region ----
    __syncthreads();
    {
        const uint32_t wbase = sb + WPROJ_OFF;
        #pragma unroll
        for (int i = 0; i < 8; i++) {            // 128 rows x 16 chunks = 2048
            int idx = tid + i * 256;
            int r = idx >> 4;
            int j = idx & 15;
            cp_async16(wbase + r * 272 + j * 16, Wr + r * 128 + j * 8);
        }
        CP_COMMIT();
    }
    #pragma unroll
    for (int mt = 0; mt < 2; mt++) {
        #pragma unroll
        for (int nt = 0; nt < 8; nt++) {
            #pragma unroll
            for (int h2 = 0; h2 < 2; h2++) {
                const int row = wm + mt * 16 + g + h2 * 8;
                const int col = wn + nt * 8 + t * 2;
                __half2 v = __floats2half2_rn(acc[mt][nt][h2 * 2 + 0] * INV_ADJ_SCALE,
                                              acc[mt][nt][h2 * 2 + 1] * INV_ADJ_SCALE);
                *reinterpret_cast<__half2*>(dsm + row * (SB_H * 2) + col * 2) = v;
            }
        }
    }
    CP_WAIT0();
    __syncthreads();

    // ---- on-chip projection: acc = aggS @ W  (K = 128) ----
    #pragma unroll
    for (int mt = 0; mt < 2; mt++)
        #pragma unroll
        for (int nt = 0; nt < 8; nt++)
            #pragma unroll
            for (int i = 0; i < 4; i++)
                acc[mt][nt][i] = 0.0f;

    #pragma unroll
    for (int ks = 0; ks < HDIM; ks += 16) {
        uint32_t af[2][4];
        #pragma unroll
        for (int mt = 0; mt < 2; mt++) {
            uint32_t addr = sb + 2u * ((wm + mt * 16 + lrow) * SB_H + ks + 8 * lhi);
            ldsm_x4(af[mt], addr);
        }
        #pragma unroll
        for (int np = 0; np < 4; np++) {
            uint32_t bf[4];
            uint32_t addr = sb + WPROJ_OFF +
                2u * ((ks + lrow) * SB_H + wn + np * 16 + 8 * lhi);
            ldsm_x4_t(bf, addr);
            #pragma unroll
            for (int mt = 0; mt < 2; mt++) {
                mma_fp16(acc[mt][2 * np + 0], af[mt], bf[0], bf[1]);
                mma_fp16(acc[mt][2 * np + 1], af[mt], bf[2], bf[3]);
            }
        }
    }

    // ---- final epilogue ----
    #pragma unroll
    for (int mt = 0; mt < 2; mt++) {
        #pragma unroll
        for (int nt = 0; nt < 8; nt++) {
            #pragma unroll
            for (int h2 = 0; h2 < 2; h2++) {
                const int row = wm + mt * 16 + g + h2 * 8;
                const int col = wn + nt * 8 + t * 2;
                float v0 = acc[mt][nt][h2 * 2 + 0] + bias[col];
                float v1 = acc[mt][nt][h2 * 2 + 1] + bias[col + 1];
                const long long off = (long long)row * HDIM + col;
                if (EULER == 0) {
                    v0 = fmaxf(v0, 0.0f);
                    v1 = fmaxf(v1, 0.0f);
                    *reinterpret_cast<__half2*>(&Chb[off]) = __floats2half2_rn(v0, v1);
                } else {
                    float2 hin = *reinterpret_cast<const float2*>(&hb[off]);
                    float2 o = { hin.x + 0.25f * fmaxf(v0, 0.0f),
                                 hin.y + 0.25f * fmaxf(v1, 0.0f) };
                    *reinterpret_cast<float2*>(&hb[off]) = o;
                    *reinterpret_cast<__half2*>(&Chb[off]) = __floats2half2_rn(o.x, o.y);
                }
            }
        }
    }
}

// ===========================================================================
// fc kernel: h = x @ W_fc + b_fc (fp32 out + fp16 shadow). K = 64, 2 stages.
// ===========================================================================
__global__ __launch_bounds__(256, 2)
void fc_kernel(const __half* __restrict__ A, const __half* __restrict__ Bg,
               float* __restrict__ Cf, __half* __restrict__ Ch,
               const float* __restrict__ bias)
{
    extern __shared__ __align__(16) char dsm[];
    const uint32_t sb = (uint32_t)__cvta_generic_to_shared(dsm);
    const int K = INDIM;

    const int tid  = threadIdx.x;
    const int lane = tid & 31;
    const int warp = tid >> 5;
    const int wm = (warp & 3) * 32;
    const int wn = (warp >> 2) * 64;
    const int g = lane >> 2;
    const int t = lane & 3;
    const int lrow = lane & 15;
    const int lhi  = lane >> 4;

    const int bm = blockIdx.y * BM;
    const __half* Ab = A + (long long)bm * K;

    float acc[2][8][4];
    #pragma unroll
    for (int mt = 0; mt < 2; mt++)
        #pragma unroll
        for (int nt = 0; nt < 8; nt++)
            #pragma unroll
            for (int i = 0; i < 4; i++)
                acc[mt][nt][i] = 0.0f;

    auto load_stage = [&](int s, int kt) {
        const uint32_t abase = sb + s * STAGE_BYTES;
        #pragma unroll
        for (int i = 0; i < 2; i++) {
            int idx = tid + i * 256;
            int r = idx >> 2;
            int j = idx & 3;
            cp_async16(abase + r * 80 + j * 16,
                       Ab + (long long)r * K + kt * 32 + j * 8);
        }
        const uint32_t bbase = abase + 10240;
        #pragma unroll
        for (int i = 0; i < 2; i++) {
            int idx = tid + i * 256;
            int r = idx >> 4;
            int j = idx & 15;
            cp_async16(bbase + r * 272 + j * 16,
                       Bg + (long long)(kt * 32 + r) * 128 + j * 8);
        }
        CP_COMMIT();
    };

    auto compute_stage = [&](int s) {
        const uint32_t abase = sb + s * STAGE_BYTES;
        const uint32_t bbase = abase + 10240;
        #pragma unroll
        for (int ks = 0; ks < 32; ks += 16) {
            uint32_t af[2][4];
            #pragma unroll
            for (int mt = 0; mt < 2; mt++) {
                uint32_t addr = abase +
                    2u * ((wm + mt * 16 + lrow) * SA_H + ks + 8 * lhi);
                ldsm_x4(af[mt], addr);
            }
            #pragma unroll
            for (int np = 0; np < 4; np++) {
                uint32_t bf[4];
                uint32_t addr = bbase +
                    2u * ((ks + lrow) * SB_H + wn + np * 16 + 8 * lhi);
                ldsm_x4_t(bf, addr);
                #pragma unroll
                for (int mt = 0; mt < 2; mt++) {
                    mma_fp16(acc[mt][2 * np + 0], af[mt], bf[0], bf[1]);
                    mma_fp16(acc[mt][2 * np + 1], af[mt], bf[2], bf[3]);
                }
            }
        }
    };

    load_stage(0, 0);
    load_stage(1, 1);
    CP_WAIT0();
    __syncthreads();
    compute_stage(0);
    compute_stage(1);

    #pragma unroll
    for (int mt = 0; mt < 2; mt++) {
        #pragma unroll
        for (int nt = 0; nt < 8; nt++) {
            #pragma unroll
            for (int h2 = 0; h2 < 2; h2++) {
                const int row = bm + wm + mt * 16 + g + h2 * 8;
                const int col = wn + nt * 8 + t * 2;
                float2 o = { acc[mt][nt][h2 * 2 + 0] + bias[col],
                             acc[mt][nt][h2 * 2 + 1] + bias[col + 1] };
                const long long off = (long long)row * HDIM + col;
                *reinterpret_cast<float2*>(&Cf[off]) = o;
                *reinterpret_cast<__half2*>(&Ch[off]) = __floats2half2_rn(o.x, o.y);
            }
        }
    }
}

extern "C" void kernel_launch(void* const* d_in, const int* in_sizes, int n_in,
                              void* d_out, int out_size)
{
    const float* x    = (const float*)d_in[0];
    const float* adj  = (const float*)d_in[1];
    const float* W_fc = (const float*)d_in[2];
    const float* b_fc = (const float*)d_in[3];
    const float* W1   = (const float*)d_in[4];
    const float* b1   = (const float*)d_in[5];
    const float* W2   = (const float*)d_in[6];
    const float* b2   = (const float*)d_in[7];
    float* out = (float*)d_out;

    __half* base;
    cudaGetSymbolAddress((void**)&base, g_h16);
    __half* tsh   = base;                      // fp16 t (gcn1 output)
    __half* hsh   = base + BNHs;               // fp16 shadow of h
    __half* adj_h = base + 2 * BNHs;
    __half* x_h   = base + 3 * BNHs;
    __half* wfc_h = base + 3 * BNHs + BNHs / 2;
    __half* w1_h  = wfc_h + INDIM * HDIM;
    __half* w2_h  = w1_h + HDIM * HDIM;
    float* h = out;    // fp32 Euler state

    cudaFuncSetAttribute(gcn_fused_kernel<0>, cudaFuncAttributeMaxDynamicSharedMemorySize, FUSED_SMEM_BYTES);
    cudaFuncSetAttribute(gcn_fused_kernel<1>, cudaFuncAttributeMaxDynamicSharedMemorySize, FUSED_SMEM_BYTES);
    cudaFuncSetAttribute(fc_kernel, cudaFuncAttributeMaxDynamicSharedMemorySize, 2 * STAGE_BYTES);

    // fp32 -> fp16 conversions (adj pre-scaled by 4096).
    {
        const int thr = 256;
        int n4 = (NNODE * NNODE) / 4;
        convert_half_kernel<<<(n4 + thr - 1) / thr, thr>>>(adj, adj_h, n4, ADJ_SCALE);
        n4 = (BATCH * NNODE * INDIM) / 4;
        convert_half_kernel<<<(n4 + thr - 1) / thr, thr>>>(x, x_h, n4, 1.0f);
        n4 = (INDIM * HDIM) / 4;
        convert_half_kernel<<<(n4 + thr - 1) / thr, thr>>>(W_fc, wfc_h, n4, 1.0f);
        n4 = (HDIM * HDIM) / 4;
        convert_half_kernel<<<(n4 + thr - 1) / thr, thr>>>(W1, w1_h, n4, 1.0f);
        convert_half_kernel<<<(n4 + thr - 1) / thr, thr>>>(W2, w2_h, n4, 1.0f);
    }

    dim3 blk(256);
    const dim3 fgrid(1, NNODE / BM, BATCH);

    // h = x @ W_fc + b_fc  (fp32 h + fp16 shadow hsh)
    fc_kernel<<<dim3(1, (BATCH * NNODE) / BM, 1), blk, 2 * STAGE_BYTES>>>(
        x_h, wfc_h, h, hsh, b_fc);

    for (int step = 0; step < 4; step++) {
        // tsh = fp16(relu((adj @ hsh) @ W1 + b1))      [reads hsh, writes tsh]
        gcn_fused_kernel<0><<<fgrid, blk, FUSED_SMEM_BYTES>>>(
            adj_h, hsh, w1_h, b1, tsh, nullptr);
        // h += 0.25*relu((adj @ tsh) @ W2 + b2); hsh = fp16(h)   [reads tsh, writes hsh]
        gcn_fused_kernel<1><<<fgrid, blk, FUSED_SMEM_BYTES>>>(
            adj_h, tsh, w2_h, b2, hsh, h);
    }
}